// round 14
// baseline (speedup 1.0000x reference)
#include <cuda_runtime.h>
#include <cuda_bf16.h>
#include <cstdint>

#define BB   64
#define TT   512
#define DD   128
#define HH   256
#define G4H  1024

typedef unsigned long long u64;

// ---------------------------------------------------------------------------
// Device scratch
// ---------------------------------------------------------------------------
// gx, interleaved per-cell: [((t*64+b)*256 + hg)*12 + q*4 + g], q: 0=v,1=l,2=u
__device__ float g_Gx[(size_t)BB * TT * HH * 12];
// h exchange, consumer-ready: [((pp*8+gb)*256 + k)*24 + comp*8 + b]
__device__ __align__(16) float g_Hx[2 * 8 * HH * 24];
__device__ unsigned int g_done[128 * 8];        // per-(gb,hc) release flag, 32B padded
__device__ unsigned int g_epoch;

// ---------------------------------------------------------------------------
// Helpers
// ---------------------------------------------------------------------------
__device__ __forceinline__ u64 pk(float lo, float hi) {
    u64 r; asm("mov.b64 %0, {%1,%2};" : "=l"(r) : "f"(lo), "f"(hi)); return r;
}
__device__ __forceinline__ u64 fma2(u64 a, u64 b, u64 c) {
    u64 d; asm("fma.rn.f32x2 %0, %1, %2, %3;" : "=l"(d) : "l"(a), "l"(b), "l"(c)); return d;
}
__device__ __forceinline__ u64 add2(u64 a, u64 b) {
    u64 d; asm("add.rn.f32x2 %0, %1, %2;" : "=l"(d) : "l"(a), "l"(b)); return d;
}
__device__ __forceinline__ void upk(u64 v, float& lo, float& hi) {
    asm("mov.b64 {%0,%1}, %2;" : "=f"(lo), "=f"(hi) : "l"(v));
}
__device__ __forceinline__ float4 ldcg4(const float4* p) {
    float4 f;
    asm volatile("ld.global.cg.v4.f32 {%0,%1,%2,%3}, [%4];"
                 : "=f"(f.x), "=f"(f.y), "=f"(f.z), "=f"(f.w) : "l"(p) : "memory");
    return f;
}
__device__ __forceinline__ unsigned int ldacq(const unsigned int* p) {
    unsigned int v;
    asm volatile("ld.acquire.gpu.global.u32 %0, [%1];" : "=r"(v) : "l"(p) : "memory");
    return v;
}
__device__ __forceinline__ float sigf(float x) {
    return __fdividef(1.0f, 1.0f + __expf(-x));
}
__device__ __forceinline__ float tanhf_(float x) {
    return __fdividef(2.0f, 1.0f + __expf(-2.0f * x)) - 1.0f;
}
__device__ __forceinline__ float min4f(float a, float b, float c, float d) {
    return fminf(fminf(a, b), fminf(c, d));
}
__device__ __forceinline__ float max4f(float a, float b, float c, float d) {
    return fmaxf(fmaxf(a, b), fmaxf(c, d));
}

// ---------------------------------------------------------------------------
// Kernel 1: gx interval GEMM (FFMA2). Interleaved per-cell output. Bumps epoch.
// ---------------------------------------------------------------------------
#define GM 64
#define GN 64
#define GK 16

__global__ __launch_bounds__(256) void gx_gemm_kernel(
    const float* __restrict__ xv, const float* __restrict__ xl,
    const float* __restrict__ xu, const float* __restrict__ W,
    const float* __restrict__ bias)
{
    if (blockIdx.x == 0 && blockIdx.y == 0 && threadIdx.x == 0)
        g_epoch = g_epoch + 1u;

    __shared__ float sAvD[GK][2 * GM + 4];
    __shared__ float sAmD[GK][2 * GM + 4];
    __shared__ float sArD[GK][2 * GM + 4];
    __shared__ float sB [GK][GN + 4];
    __shared__ float sBa[GK][GN + 4];

    const int n0 = blockIdx.x * GN;
    const int m0 = blockIdx.y * GM;
    const int tid = threadIdx.x;
    const int tx = tid & 15;
    const int ty = tid >> 4;

    u64 accv[4][2], accm[4][2], accr[4][2];
#pragma unroll
    for (int i = 0; i < 4; i++)
#pragma unroll
        for (int j = 0; j < 2; j++) { accv[i][j] = 0ull; accm[i][j] = 0ull; accr[i][j] = 0ull; }

    const int ml = tid >> 2;
    const int kq = tid & 3;

    for (int k0 = 0; k0 < DD; k0 += GK) {
        {
            const float4 v4 = *(const float4*)(xv + (size_t)(m0 + ml) * DD + k0 + kq * 4);
            const float4 l4 = *(const float4*)(xl + (size_t)(m0 + ml) * DD + k0 + kq * 4);
            const float4 u4 = *(const float4*)(xu + (size_t)(m0 + ml) * DD + k0 + kq * 4);
            const float vv[4] = {v4.x, v4.y, v4.z, v4.w};
            const float ll[4] = {l4.x, l4.y, l4.z, l4.w};
            const float uu[4] = {u4.x, u4.y, u4.z, u4.w};
#pragma unroll
            for (int j = 0; j < 4; j++) {
                const int k = kq * 4 + j;
                const float mu = 0.5f * (ll[j] + uu[j]);
                const float rr = 0.5f * (uu[j] - ll[j]);
                ((float2*)&sAvD[k][0])[ml] = make_float2(vv[j], vv[j]);
                ((float2*)&sAmD[k][0])[ml] = make_float2(mu, mu);
                ((float2*)&sArD[k][0])[ml] = make_float2(rr, rr);
            }
        }
        {
            const float4 w4 = *(const float4*)(W + (size_t)(n0 + ml) * DD + k0 + kq * 4);
            const float ww[4] = {w4.x, w4.y, w4.z, w4.w};
#pragma unroll
            for (int j = 0; j < 4; j++) {
                sB [kq * 4 + j][ml] = ww[j];
                sBa[kq * 4 + j][ml] = fabsf(ww[j]);
            }
        }
        __syncthreads();

#pragma unroll
        for (int k = 0; k < GK; k++) {
            const u64 b01 = *(const u64*)&sB [k][tx * 4];
            const u64 b23 = *(const u64*)&sB [k][tx * 4 + 2];
            const u64 a01 = *(const u64*)&sBa[k][tx * 4];
            const u64 a23 = *(const u64*)&sBa[k][tx * 4 + 2];
#pragma unroll
            for (int i = 0; i < 4; i++) {
                const u64 av = *(const u64*)&sAvD[k][2 * (4 * ty + i)];
                const u64 am = *(const u64*)&sAmD[k][2 * (4 * ty + i)];
                const u64 ar = *(const u64*)&sArD[k][2 * (4 * ty + i)];
                accv[i][0] = fma2(av, b01, accv[i][0]);
                accv[i][1] = fma2(av, b23, accv[i][1]);
                accm[i][0] = fma2(am, b01, accm[i][0]);
                accm[i][1] = fma2(am, b23, accm[i][1]);
                accr[i][0] = fma2(ar, a01, accr[i][0]);
                accr[i][1] = fma2(ar, a23, accr[i][1]);
            }
        }
        __syncthreads();
    }

    float bb4[4];
#pragma unroll
    for (int j = 0; j < 4; j++) bb4[j] = bias[n0 + tx * 4 + j];
#pragma unroll
    for (int i = 0; i < 4; i++) {
        const int m = m0 + ty * 4 + i;
        const int bI = m >> 9;          // batch
        const int tI = m & 511;         // time
        const size_t cellbase = (size_t)(tI * 64 + bI) * (HH * 12);
        float v[4], q[4], r[4];
        upk(accv[i][0], v[0], v[1]); upk(accv[i][1], v[2], v[3]);
        upk(accm[i][0], q[0], q[1]); upk(accm[i][1], q[2], q[3]);
        upk(accr[i][0], r[0], r[1]); upk(accr[i][1], r[2], r[3]);
#pragma unroll
        for (int j = 0; j < 4; j++) {
            const int n = n0 + tx * 4 + j;
            const int gI = n >> 8;           // gate 0..3
            const int hgx = n & 255;         // h index
            float* p = g_Gx + cellbase + hgx * 12 + gI;
            const float vv = v[j] + bb4[j];
            const float mu = q[j] + bb4[j];
            p[0] = vv;
            p[4] = mu - r[j];
            p[8] = mu + r[j];
        }
    }
}

// ---------------------------------------------------------------------------
// Kernel 2: persistent scan = R12 body + vectorized exchange paths.
// 128 CTAs x 512 thr. kgroup g (64 thr) polls its 2 producer flags, raw-copies
// its 32-k slice (3x float4/thread), named-barrier(8+g), k-loop from smem.
// ---------------------------------------------------------------------------
#define NCTA 128
#define NTHR 512
#define KSL  32

// smem float offsets:
//  sH   [0,     6144)  : float [256 k][24] = (hv[8], hm[8], hr[8])
//  sRed [6144,  18432) : u64 [12 j][8 kgr][64 m]
//  sT   [18432, 19968) : u64 [12][64]
#define SM_RED 6144
#define SM_T   18432
#define SMEM_FLOATS 19968

__global__ __launch_bounds__(NTHR, 1) void scan_kernel(
    const float* __restrict__ Whh, const float* __restrict__ h0,
    const float* __restrict__ c0, float* __restrict__ out)
{
    extern __shared__ float smem[];
    float* sH   = smem;
    u64*   sRed = (u64*)(smem + SM_RED);
    u64*   sT   = (u64*)(smem + SM_T);
    float* sTf  = (float*)sT;

    const int tid = threadIdx.x;
    const int gb = blockIdx.x >> 4;      // batch group 0..7
    const int hc = blockIdx.x & 15;      // h chunk 0..15
    const int kgr = tid >> 6;            // kgroup 0..7
    const int m = tid & 63;              // gate-row 0..63
    const int hL = m >> 2;               // 0..15
    const int g  = m & 3;                // 0..3
    const int kbase = kgr * KSL;

    const unsigned int ep512 = (*(volatile unsigned int*)&g_epoch) * 512u;

    // --- W slice into registers (forever) ---
    float wreg[KSL];
    {
        const float* wrow = Whh + (size_t)(g * HH + hc * 16 + hL) * HH + kbase;
#pragma unroll
        for (int i = 0; i < KSL / 4; i++) {
            const float4 w4 = *(const float4*)(wrow + 4 * i);
            wreg[4 * i + 0] = w4.x; wreg[4 * i + 1] = w4.y;
            wreg[4 * i + 2] = w4.z; wreg[4 * i + 3] = w4.w;
        }
    }

    // --- pointwise cell state (tid < 128): cell (ph, pb) ---
    const int pb = tid & 7;
    const int ph = (tid >> 3) & 15;
    const int bglob = gb * 8 + pb;
    const int hg = hc * 16 + ph;
    float cv = 0.f, cl = 0.f, cu = 0.f;
    if (tid < 128) { cv = c0[bglob * HH + hg]; cl = cv; cu = cv; }

    unsigned int* myflag = &g_done[(gb * 16 + hc) * 8];
    const unsigned int* flag0 = &g_done[(gb * 16 + 2 * kgr) * 8];
    const unsigned int* flag1 = &g_done[(gb * 16 + 2 * kgr + 1) * 8];

    // --- pre-loop: stage h0 (all threads) ---
    for (int idx = tid; idx < 2048; idx += NTHR) {
        const int k = idx >> 3, bb = idx & 7;
        const float v = h0[(gb * 8 + bb) * HH + k];
        sH[k * 24 + bb]      = v;
        sH[k * 24 + 8 + bb]  = v;
        sH[k * 24 + 16 + bb] = 0.f;
    }
    __syncthreads();

    for (int t = 0; t < TT; t++) {
        // gx prefetch for this step (tid<128, 3 LDG.128; issued before polls)
        float4 gxq0, gxq1, gxq2;
        if (tid < 128) {
            const float4* gp = (const float4*)(g_Gx +
                ((size_t)(t * 64 + bglob) * HH + hg) * 12);
            gxq0 = __ldcs(gp);
            gxq1 = __ldcs(gp + 1);
            gxq2 = __ldcs(gp + 2);
        }

        if (t > 0) {
            // kgroup-granular: wait for my 2 producers, raw-copy my k slice
            const unsigned int want = ep512 + (unsigned)(t - 1);
            while ((int)(ldacq(flag0) - want) < 0) { }
            while ((int)(ldacq(flag1) - want) < 0) { }
            const float4* src = (const float4*)g_Hx +
                (size_t)(((t - 1) & 1) * 8 + gb) * (HH * 6) + kbase * 6;
            float4* dst = (float4*)sH + kbase * 6;
#pragma unroll
            for (int j = 0; j < 3; j++) {
                const int f = j * 64 + m;      // 0..191, lane-contiguous
                dst[f] = ldcg4(src + f);
            }
            // sync the 64 threads of this kgroup only
            asm volatile("bar.sync %0, %1;" :: "r"(8 + kgr), "r"(64) : "memory");
        }

        // --- k-loop: 32 iters, 6 broadcast LDS.128 + 12 FFMA2, W in regs ---
        u64 accv[4] = {0ull, 0ull, 0ull, 0ull};
        u64 accm[4] = {0ull, 0ull, 0ull, 0ull};
        u64 accr[4] = {0ull, 0ull, 0ull, 0ull};
#pragma unroll
        for (int kk = 0; kk < KSL; kk++) {
            const ulonglong2* hk = (const ulonglong2*)(sH + (kbase + kk) * 24);
            const ulonglong2 hva = hk[0];
            const ulonglong2 hvb = hk[1];
            const ulonglong2 hma = hk[2];
            const ulonglong2 hmb = hk[3];
            const ulonglong2 hra = hk[4];
            const ulonglong2 hrb = hk[5];
            const float w = wreg[kk];
            const u64 wd = pk(w, w);
            const u64 wa = wd & 0x7FFFFFFF7FFFFFFFull;
            accv[0] = fma2(hva.x, wd, accv[0]);
            accv[1] = fma2(hva.y, wd, accv[1]);
            accv[2] = fma2(hvb.x, wd, accv[2]);
            accv[3] = fma2(hvb.y, wd, accv[3]);
            accm[0] = fma2(hma.x, wd, accm[0]);
            accm[1] = fma2(hma.y, wd, accm[1]);
            accm[2] = fma2(hmb.x, wd, accm[2]);
            accm[3] = fma2(hmb.y, wd, accm[3]);
            accr[0] = fma2(hra.x, wa, accr[0]);
            accr[1] = fma2(hra.y, wa, accr[1]);
            accr[2] = fma2(hrb.x, wa, accr[2]);
            accr[3] = fma2(hrb.y, wa, accr[3]);
        }

        // publish partials, conflict-free layout sRed[j*512 + tid], j = comp*4+p
#pragma unroll
        for (int p = 0; p < 4; p++) {
            sRed[(0 * 4 + p) * 512 + tid] = accv[p];
            sRed[(1 * 4 + p) * 512 + tid] = accm[p];
            sRed[(2 * 4 + p) * 512 + tid] = accr[p];
        }
        __syncthreads();

        // reduce (tid < 256): thread (rq 0..3, rm 0..63) sums 3 u64 over 8 kgroups
        if (tid < 256) {
            const int rm = tid & 63;
            const int rq = tid >> 6;
            u64 B0 = 0ull, B1 = 0ull, B2 = 0ull;
#pragma unroll
            for (int s = 0; s < 8; s++) {
                const u64* p = sRed + s * 64 + rm;
                B0 = add2(B0, p[(3 * rq + 0) * 512]);
                B1 = add2(B1, p[(3 * rq + 1) * 512]);
                B2 = add2(B2, p[(3 * rq + 2) * 512]);
            }
            const int rg = rm & 3, rh = rm >> 2;
#pragma unroll
            for (int jj = 0; jj < 3; jj++) {
                const int j = 3 * rq + jj;
                const u64 Bv = (jj == 0) ? B0 : (jj == 1) ? B1 : B2;
                sT[((j >> 2) * 4 + rg) * 64 + rh * 4 + (j & 3)] = Bv;
            }
        }
        __syncthreads();

        // pointwise (tid < 128)
        float hn_v = 0.f, hn_l = 0.f, hn_u = 0.f;
        if (tid < 128) {
            const int co = ph * 8 + pb;
            const float av0 = sTf[0 * 128 + co], av1 = sTf[1 * 128 + co];
            const float av2 = sTf[2 * 128 + co], av3 = sTf[3 * 128 + co];
            const float am0 = sTf[4 * 128 + co], am1 = sTf[5 * 128 + co];
            const float am2 = sTf[6 * 128 + co], am3 = sTf[7 * 128 + co];
            const float ar0 = sTf[8 * 128 + co], ar1 = sTf[9 * 128 + co];
            const float ar2 = sTf[10 * 128 + co], ar3 = sTf[11 * 128 + co];

            const float pv0 = gxq0.x + av0, pl0 = gxq1.x + am0 - ar0, pu0 = gxq2.x + am0 + ar0;
            const float pv1 = gxq0.y + av1, pl1 = gxq1.y + am1 - ar1, pu1 = gxq2.y + am1 + ar1;
            const float pv2 = gxq0.z + av2, pl2 = gxq1.z + am2 - ar2, pu2 = gxq2.z + am2 + ar2;
            const float pv3 = gxq0.w + av3, pl3 = gxq1.w + am3 - ar3, pu3 = gxq2.w + am3 + ar3;

            const float iv = sigf(pv0), il = sigf(pl0), iu = sigf(pu0);
            const float fv = sigf(pv1), fl = sigf(pl1), fu = sigf(pu1);
            const float gv = tanhf_(pv2), gl = tanhf_(pl2), gu = tanhf_(pu2);
            const float ov = sigf(pv3), ol = sigf(pl3), ou = sigf(pu3);

            const float t1 = fl * cl, t2 = fl * cu, t3 = fu * cl, t4 = fu * cu;
            const float s1 = il * gl, s2 = il * gu, s3 = iu * gl, s4 = iu * gu;
            cv = fv * cv + iv * gv;
            cl = min4f(t1, t2, t3, t4) + min4f(s1, s2, s3, s4);
            cu = max4f(t1, t2, t3, t4) + max4f(s1, s2, s3, s4);

            const float tv = tanhf_(cv), tl = tanhf_(cl), tu = tanhf_(cu);
            const float u1 = ol * tl, u2 = ol * tu, u3 = ou * tl, u4 = ou * tu;
            hn_l = min4f(u1, u2, u3, u4);
            hn_u = max4f(u1, u2, u3, u4);
            hn_v = ov * tv;

            // publish h in consumer-ready layout (v, m, r planes)
            const float hm = 0.5f * (hn_l + hn_u);
            const float hr = 0.5f * (hn_u - hn_l);
            float* dp = g_Hx + (size_t)((t & 1) * 8 + gb) * (HH * 24) + hg * 24 + pb;
            __stcg(dp,      hn_v);
            __stcg(dp + 8,  hm);
            __stcg(dp + 16, hr);
        }
        __syncthreads();   // all h stores ordered before flag release

        if (tid == 0)
            asm volatile("st.release.gpu.global.u32 [%0], %1;"
                         :: "l"(myflag), "r"(ep512 + (unsigned)t) : "memory");

        // output stores off the critical path
        if (tid < 128) {
            const size_t obase = ((size_t)(bglob << 9) + t) * HH + hg;
            out[obase] = hn_v;
            out[(size_t)BB * TT * HH + obase] = hn_l;
            out[2 * (size_t)BB * TT * HH + obase] = hn_u;
        }
    }
}

// ---------------------------------------------------------------------------
// Launch
// ---------------------------------------------------------------------------
extern "C" void kernel_launch(void* const* d_in, const int* in_sizes, int n_in,
                              void* d_out, int out_size)
{
    const float* xv   = (const float*)d_in[0];
    const float* xl   = (const float*)d_in[1];
    const float* xu   = (const float*)d_in[2];
    const float* Wih  = (const float*)d_in[3];
    const float* Whh  = (const float*)d_in[4];
    const float* bias = (const float*)d_in[5];
    const float* h0   = (const float*)d_in[6];
    const float* c0   = (const float*)d_in[7];
    float* out = (float*)d_out;

    const int smem_bytes = SMEM_FLOATS * sizeof(float);   // ~80 KB
    cudaFuncSetAttribute(scan_kernel, cudaFuncAttributeMaxDynamicSharedMemorySize, smem_bytes);

    gx_gemm_kernel<<<dim3(G4H / GN, (BB * TT) / GM), 256>>>(xv, xl, xu, Wih, bias);
    scan_kernel<<<NCTA, NTHR, smem_bytes>>>(Whh, h0, c0, out);
}

// round 15
// speedup vs baseline: 1.0839x; 1.0839x over previous
#include <cuda_runtime.h>
#include <cuda_bf16.h>
#include <cstdint>

#define BB   64
#define TT   512
#define DD   128
#define HH   256
#define G4H  1024

typedef unsigned long long u64;

// ---------------------------------------------------------------------------
// Device scratch
// ---------------------------------------------------------------------------
__device__ float g_Gv[(size_t)BB * TT * G4H];   // time-major: [(t*64+b)*1024 + n]
__device__ float g_Gl[(size_t)BB * TT * G4H];
__device__ float g_Gu[(size_t)BB * TT * G4H];
// h exchange, consumer-ready: [((pp*8+gb)*256 + k)*24 + comp*8 + b]
__device__ __align__(16) float g_Hx[2 * 8 * HH * 24];
__device__ unsigned int g_done[128 * 8];        // per-(gb,hc) release flag, 32B padded
__device__ unsigned int g_epoch;

// ---------------------------------------------------------------------------
// Helpers
// ---------------------------------------------------------------------------
__device__ __forceinline__ u64 pk(float lo, float hi) {
    u64 r; asm("mov.b64 %0, {%1,%2};" : "=l"(r) : "f"(lo), "f"(hi)); return r;
}
__device__ __forceinline__ u64 fma2(u64 a, u64 b, u64 c) {
    u64 d; asm("fma.rn.f32x2 %0, %1, %2, %3;" : "=l"(d) : "l"(a), "l"(b), "l"(c)); return d;
}
__device__ __forceinline__ u64 add2(u64 a, u64 b) {
    u64 d; asm("add.rn.f32x2 %0, %1, %2;" : "=l"(d) : "l"(a), "l"(b)); return d;
}
__device__ __forceinline__ void upk(u64 v, float& lo, float& hi) {
    asm("mov.b64 {%0,%1}, %2;" : "=f"(lo), "=f"(hi) : "l"(v));
}
__device__ __forceinline__ float4 ldcg4(const float4* p) {
    float4 f;
    asm volatile("ld.global.cg.v4.f32 {%0,%1,%2,%3}, [%4];"
                 : "=f"(f.x), "=f"(f.y), "=f"(f.z), "=f"(f.w) : "l"(p) : "memory");
    return f;
}
__device__ __forceinline__ unsigned int ldacq(const unsigned int* p) {
    unsigned int v;
    asm volatile("ld.acquire.gpu.global.u32 %0, [%1];" : "=r"(v) : "l"(p) : "memory");
    return v;
}
__device__ __forceinline__ float sigf(float x) {
    return __fdividef(1.0f, 1.0f + __expf(-x));
}
__device__ __forceinline__ float tanhf_(float x) {
    return __fdividef(2.0f, 1.0f + __expf(-2.0f * x)) - 1.0f;
}
__device__ __forceinline__ float min4f(float a, float b, float c, float d) {
    return fminf(fminf(a, b), fminf(c, d));
}
__device__ __forceinline__ float max4f(float a, float b, float c, float d) {
    return fmaxf(fmaxf(a, b), fmaxf(c, d));
}

// ---------------------------------------------------------------------------
// Kernel 1: gx interval GEMM (FFMA2). Time-major float4 output. Bumps epoch.
// ---------------------------------------------------------------------------
#define GM 64
#define GN 64
#define GK 16

__global__ __launch_bounds__(256) void gx_gemm_kernel(
    const float* __restrict__ xv, const float* __restrict__ xl,
    const float* __restrict__ xu, const float* __restrict__ W,
    const float* __restrict__ bias)
{
    if (blockIdx.x == 0 && blockIdx.y == 0 && threadIdx.x == 0)
        g_epoch = g_epoch + 1u;

    __shared__ float sAvD[GK][2 * GM + 4];
    __shared__ float sAmD[GK][2 * GM + 4];
    __shared__ float sArD[GK][2 * GM + 4];
    __shared__ float sB [GK][GN + 4];
    __shared__ float sBa[GK][GN + 4];

    const int n0 = blockIdx.x * GN;
    const int m0 = blockIdx.y * GM;
    const int tid = threadIdx.x;
    const int tx = tid & 15;
    const int ty = tid >> 4;

    u64 accv[4][2], accm[4][2], accr[4][2];
#pragma unroll
    for (int i = 0; i < 4; i++)
#pragma unroll
        for (int j = 0; j < 2; j++) { accv[i][j] = 0ull; accm[i][j] = 0ull; accr[i][j] = 0ull; }

    const int ml = tid >> 2;
    const int kq = tid & 3;

    for (int k0 = 0; k0 < DD; k0 += GK) {
        {
            const float4 v4 = *(const float4*)(xv + (size_t)(m0 + ml) * DD + k0 + kq * 4);
            const float4 l4 = *(const float4*)(xl + (size_t)(m0 + ml) * DD + k0 + kq * 4);
            const float4 u4 = *(const float4*)(xu + (size_t)(m0 + ml) * DD + k0 + kq * 4);
            const float vv[4] = {v4.x, v4.y, v4.z, v4.w};
            const float ll[4] = {l4.x, l4.y, l4.z, l4.w};
            const float uu[4] = {u4.x, u4.y, u4.z, u4.w};
#pragma unroll
            for (int j = 0; j < 4; j++) {
                const int k = kq * 4 + j;
                const float mu = 0.5f * (ll[j] + uu[j]);
                const float rr = 0.5f * (uu[j] - ll[j]);
                ((float2*)&sAvD[k][0])[ml] = make_float2(vv[j], vv[j]);
                ((float2*)&sAmD[k][0])[ml] = make_float2(mu, mu);
                ((float2*)&sArD[k][0])[ml] = make_float2(rr, rr);
            }
        }
        {
            const float4 w4 = *(const float4*)(W + (size_t)(n0 + ml) * DD + k0 + kq * 4);
            const float ww[4] = {w4.x, w4.y, w4.z, w4.w};
#pragma unroll
            for (int j = 0; j < 4; j++) {
                sB [kq * 4 + j][ml] = ww[j];
                sBa[kq * 4 + j][ml] = fabsf(ww[j]);
            }
        }
        __syncthreads();

#pragma unroll
        for (int k = 0; k < GK; k++) {
            const u64 b01 = *(const u64*)&sB [k][tx * 4];
            const u64 b23 = *(const u64*)&sB [k][tx * 4 + 2];
            const u64 a01 = *(const u64*)&sBa[k][tx * 4];
            const u64 a23 = *(const u64*)&sBa[k][tx * 4 + 2];
#pragma unroll
            for (int i = 0; i < 4; i++) {
                const u64 av = *(const u64*)&sAvD[k][2 * (4 * ty + i)];
                const u64 am = *(const u64*)&sAmD[k][2 * (4 * ty + i)];
                const u64 ar = *(const u64*)&sArD[k][2 * (4 * ty + i)];
                accv[i][0] = fma2(av, b01, accv[i][0]);
                accv[i][1] = fma2(av, b23, accv[i][1]);
                accm[i][0] = fma2(am, b01, accm[i][0]);
                accm[i][1] = fma2(am, b23, accm[i][1]);
                accr[i][0] = fma2(ar, a01, accr[i][0]);
                accr[i][1] = fma2(ar, a23, accr[i][1]);
            }
        }
        __syncthreads();
    }

    float bb4[4];
#pragma unroll
    for (int j = 0; j < 4; j++) bb4[j] = bias[n0 + tx * 4 + j];
#pragma unroll
    for (int i = 0; i < 4; i++) {
        const int m = m0 + ty * 4 + i;
        const int bI = m >> 9;          // batch
        const int tI = m & 511;         // time
        const size_t o = ((size_t)tI * 64 + bI) * G4H + n0 + tx * 4;
        float v0, v1, v2, v3, q0, q1, q2, q3, r0, r1, r2, r3;
        upk(accv[i][0], v0, v1); upk(accv[i][1], v2, v3);
        upk(accm[i][0], q0, q1); upk(accm[i][1], q2, q3);
        upk(accr[i][0], r0, r1); upk(accr[i][1], r2, r3);
        *(float4*)(g_Gv + o) = make_float4(v0 + bb4[0], v1 + bb4[1], v2 + bb4[2], v3 + bb4[3]);
        *(float4*)(g_Gl + o) = make_float4(q0 + bb4[0] - r0, q1 + bb4[1] - r1, q2 + bb4[2] - r2, q3 + bb4[3] - r3);
        *(float4*)(g_Gu + o) = make_float4(q0 + bb4[0] + r0, q1 + bb4[1] + r1, q2 + bb4[2] + r2, q3 + bb4[3] + r3);
    }
}

// ---------------------------------------------------------------------------
// Kernel 2: persistent scan = R12 body + vectorized h-exchange (R14's winner).
// 128 CTAs x 512 thr. kgroup g (64 thr) polls its 2 producer flags, raw-copies
// its 32-k slice (3x float4/thread), named-barrier(8+g), k-loop from smem.
// ---------------------------------------------------------------------------
#define NCTA 128
#define NTHR 512
#define KSL  32

// smem float offsets:
//  sH   [0,     6144)  : float [256 k][24] = (hv[8], hm[8], hr[8])
//  sRed [6144,  18432) : u64 [12 j][8 kgr][64 m]
//  sT   [18432, 19968) : u64 [12][64]
#define SM_RED 6144
#define SM_T   18432
#define SMEM_FLOATS 19968

__global__ __launch_bounds__(NTHR, 1) void scan_kernel(
    const float* __restrict__ Whh, const float* __restrict__ h0,
    const float* __restrict__ c0, float* __restrict__ out)
{
    extern __shared__ float smem[];
    float* sH   = smem;
    u64*   sRed = (u64*)(smem + SM_RED);
    u64*   sT   = (u64*)(smem + SM_T);
    float* sTf  = (float*)sT;

    const int tid = threadIdx.x;
    const int gb = blockIdx.x >> 4;      // batch group 0..7
    const int hc = blockIdx.x & 15;      // h chunk 0..15
    const int kgr = tid >> 6;            // kgroup 0..7
    const int m = tid & 63;              // gate-row 0..63
    const int hL = m >> 2;               // 0..15
    const int g  = m & 3;                // 0..3
    const int kbase = kgr * KSL;

    const unsigned int ep512 = (*(volatile unsigned int*)&g_epoch) * 512u;

    // --- W slice into registers (forever) ---
    float wreg[KSL];
    {
        const float* wrow = Whh + (size_t)(g * HH + hc * 16 + hL) * HH + kbase;
#pragma unroll
        for (int i = 0; i < KSL / 4; i++) {
            const float4 w4 = *(const float4*)(wrow + 4 * i);
            wreg[4 * i + 0] = w4.x; wreg[4 * i + 1] = w4.y;
            wreg[4 * i + 2] = w4.z; wreg[4 * i + 3] = w4.w;
        }
    }

    // --- pointwise cell state (tid < 128): cell (ph, pb) ---
    const int pb = tid & 7;
    const int ph = (tid >> 3) & 15;
    const int bglob = gb * 8 + pb;
    const int hg = hc * 16 + ph;
    float cv = 0.f, cl = 0.f, cu = 0.f;
    if (tid < 128) { cv = c0[bglob * HH + hg]; cl = cv; cu = cv; }

    unsigned int* myflag = &g_done[(gb * 16 + hc) * 8];
    const unsigned int* flag0 = &g_done[(gb * 16 + 2 * kgr) * 8];
    const unsigned int* flag1 = &g_done[(gb * 16 + 2 * kgr + 1) * 8];

    // --- pre-loop: stage h0 (all threads) ---
    for (int idx = tid; idx < 2048; idx += NTHR) {
        const int k = idx >> 3, bb = idx & 7;
        const float v = h0[(gb * 8 + bb) * HH + k];
        sH[k * 24 + bb]      = v;
        sH[k * 24 + 8 + bb]  = v;
        sH[k * 24 + 16 + bb] = 0.f;
    }
    __syncthreads();

    for (int t = 0; t < TT; t++) {
        // gx prefetch for this step (tid<128; issued before polls)
        float gxr[12];
        if (tid < 128) {
            const size_t gB = (size_t)((size_t)t * 64 + bglob) * G4H + hg;
#pragma unroll
            for (int q = 0; q < 4; q++) {
                gxr[q]     = __ldcs(g_Gv + gB + q * 256);
                gxr[4 + q] = __ldcs(g_Gl + gB + q * 256);
                gxr[8 + q] = __ldcs(g_Gu + gB + q * 256);
            }
        }

        if (t > 0) {
            // kgroup-granular: wait for my 2 producers, raw-copy my k slice
            const unsigned int want = ep512 + (unsigned)(t - 1);
            while ((int)(ldacq(flag0) - want) < 0) { }
            while ((int)(ldacq(flag1) - want) < 0) { }
            const float4* src = (const float4*)g_Hx +
                (size_t)(((t - 1) & 1) * 8 + gb) * (HH * 6) + kbase * 6;
            float4* dst = (float4*)sH + kbase * 6;
#pragma unroll
            for (int j = 0; j < 3; j++) {
                const int f = j * 64 + m;      // 0..191, lane-contiguous
                dst[f] = ldcg4(src + f);
            }
            // sync the 64 threads of this kgroup only
            asm volatile("bar.sync %0, %1;" :: "r"(8 + kgr), "r"(64) : "memory");
        }

        // --- k-loop: 32 iters, 6 broadcast LDS.128 + 12 FFMA2, W in regs ---
        u64 accv[4] = {0ull, 0ull, 0ull, 0ull};
        u64 accm[4] = {0ull, 0ull, 0ull, 0ull};
        u64 accr[4] = {0ull, 0ull, 0ull, 0ull};
#pragma unroll
        for (int kk = 0; kk < KSL; kk++) {
            const ulonglong2* hk = (const ulonglong2*)(sH + (kbase + kk) * 24);
            const ulonglong2 hva = hk[0];
            const ulonglong2 hvb = hk[1];
            const ulonglong2 hma = hk[2];
            const ulonglong2 hmb = hk[3];
            const ulonglong2 hra = hk[4];
            const ulonglong2 hrb = hk[5];
            const float w = wreg[kk];
            const u64 wd = pk(w, w);
            const u64 wa = wd & 0x7FFFFFFF7FFFFFFFull;
            accv[0] = fma2(hva.x, wd, accv[0]);
            accv[1] = fma2(hva.y, wd, accv[1]);
            accv[2] = fma2(hvb.x, wd, accv[2]);
            accv[3] = fma2(hvb.y, wd, accv[3]);
            accm[0] = fma2(hma.x, wd, accm[0]);
            accm[1] = fma2(hma.y, wd, accm[1]);
            accm[2] = fma2(hmb.x, wd, accm[2]);
            accm[3] = fma2(hmb.y, wd, accm[3]);
            accr[0] = fma2(hra.x, wa, accr[0]);
            accr[1] = fma2(hra.y, wa, accr[1]);
            accr[2] = fma2(hrb.x, wa, accr[2]);
            accr[3] = fma2(hrb.y, wa, accr[3]);
        }

        // publish partials, conflict-free layout sRed[j*512 + tid], j = comp*4+p
#pragma unroll
        for (int p = 0; p < 4; p++) {
            sRed[(0 * 4 + p) * 512 + tid] = accv[p];
            sRed[(1 * 4 + p) * 512 + tid] = accm[p];
            sRed[(2 * 4 + p) * 512 + tid] = accr[p];
        }
        __syncthreads();

        // reduce (tid < 256): thread (rq 0..3, rm 0..63) sums 3 u64 over 8 kgroups
        if (tid < 256) {
            const int rm = tid & 63;
            const int rq = tid >> 6;
            u64 B0 = 0ull, B1 = 0ull, B2 = 0ull;
#pragma unroll
            for (int s = 0; s < 8; s++) {
                const u64* p = sRed + s * 64 + rm;
                B0 = add2(B0, p[(3 * rq + 0) * 512]);
                B1 = add2(B1, p[(3 * rq + 1) * 512]);
                B2 = add2(B2, p[(3 * rq + 2) * 512]);
            }
            const int rg = rm & 3, rh = rm >> 2;
#pragma unroll
            for (int jj = 0; jj < 3; jj++) {
                const int j = 3 * rq + jj;
                const u64 Bv = (jj == 0) ? B0 : (jj == 1) ? B1 : B2;
                sT[((j >> 2) * 4 + rg) * 64 + rh * 4 + (j & 3)] = Bv;
            }
        }
        __syncthreads();

        // pointwise (tid < 128)
        float hn_v = 0.f, hn_l = 0.f, hn_u = 0.f;
        if (tid < 128) {
            const int co = ph * 8 + pb;
            const float av0 = sTf[0 * 128 + co], av1 = sTf[1 * 128 + co];
            const float av2 = sTf[2 * 128 + co], av3 = sTf[3 * 128 + co];
            const float am0 = sTf[4 * 128 + co], am1 = sTf[5 * 128 + co];
            const float am2 = sTf[6 * 128 + co], am3 = sTf[7 * 128 + co];
            const float ar0 = sTf[8 * 128 + co], ar1 = sTf[9 * 128 + co];
            const float ar2 = sTf[10 * 128 + co], ar3 = sTf[11 * 128 + co];

            const float pv0 = gxr[0] + av0, pl0 = gxr[4] + am0 - ar0, pu0 = gxr[8]  + am0 + ar0;
            const float pv1 = gxr[1] + av1, pl1 = gxr[5] + am1 - ar1, pu1 = gxr[9]  + am1 + ar1;
            const float pv2 = gxr[2] + av2, pl2 = gxr[6] + am2 - ar2, pu2 = gxr[10] + am2 + ar2;
            const float pv3 = gxr[3] + av3, pl3 = gxr[7] + am3 - ar3, pu3 = gxr[11] + am3 + ar3;

            const float iv = sigf(pv0), il = sigf(pl0), iu = sigf(pu0);
            const float fv = sigf(pv1), fl = sigf(pl1), fu = sigf(pu1);
            const float gv = tanhf_(pv2), gl = tanhf_(pl2), gu = tanhf_(pu2);
            const float ov = sigf(pv3), ol = sigf(pl3), ou = sigf(pu3);

            const float t1 = fl * cl, t2 = fl * cu, t3 = fu * cl, t4 = fu * cu;
            const float s1 = il * gl, s2 = il * gu, s3 = iu * gl, s4 = iu * gu;
            cv = fv * cv + iv * gv;
            cl = min4f(t1, t2, t3, t4) + min4f(s1, s2, s3, s4);
            cu = max4f(t1, t2, t3, t4) + max4f(s1, s2, s3, s4);

            const float tv = tanhf_(cv), tl = tanhf_(cl), tu = tanhf_(cu);
            const float u1 = ol * tl, u2 = ol * tu, u3 = ou * tl, u4 = ou * tu;
            hn_l = min4f(u1, u2, u3, u4);
            hn_u = max4f(u1, u2, u3, u4);
            hn_v = ov * tv;

            // publish h in consumer-ready layout (v, m, r planes)
            const float hm = 0.5f * (hn_l + hn_u);
            const float hr = 0.5f * (hn_u - hn_l);
            float* dp = g_Hx + (size_t)((t & 1) * 8 + gb) * (HH * 24) + hg * 24 + pb;
            __stcg(dp,      hn_v);
            __stcg(dp + 8,  hm);
            __stcg(dp + 16, hr);
        }
        __syncthreads();   // all h stores ordered before flag release

        if (tid == 0)
            asm volatile("st.release.gpu.global.u32 [%0], %1;"
                         :: "l"(myflag), "r"(ep512 + (unsigned)t) : "memory");

        // output stores off the critical path
        if (tid < 128) {
            const size_t obase = ((size_t)(bglob << 9) + t) * HH + hg;
            out[obase] = hn_v;
            out[(size_t)BB * TT * HH + obase] = hn_l;
            out[2 * (size_t)BB * TT * HH + obase] = hn_u;
        }
    }
}

// ---------------------------------------------------------------------------
// Launch
// ---------------------------------------------------------------------------
extern "C" void kernel_launch(void* const* d_in, const int* in_sizes, int n_in,
                              void* d_out, int out_size)
{
    const float* xv   = (const float*)d_in[0];
    const float* xl   = (const float*)d_in[1];
    const float* xu   = (const float*)d_in[2];
    const float* Wih  = (const float*)d_in[3];
    const float* Whh  = (const float*)d_in[4];
    const float* bias = (const float*)d_in[5];
    const float* h0   = (const float*)d_in[6];
    const float* c0   = (const float*)d_in[7];
    float* out = (float*)d_out;

    const int smem_bytes = SMEM_FLOATS * sizeof(float);   // ~80 KB
    cudaFuncSetAttribute(scan_kernel, cudaFuncAttributeMaxDynamicSharedMemorySize, smem_bytes);

    gx_gemm_kernel<<<dim3(G4H / GN, (BB * TT) / GM), 256>>>(xv, xl, xu, Wih, bias);
    scan_kernel<<<NCTA, NTHR, smem_bytes>>>(Whh, h0, c0, out);
}